// round 10
// baseline (speedup 1.0000x reference)
#include <cuda_runtime.h>
#include <cuda_fp16.h>
#include <cstdint>

#define BATCH 256
#define SEQ   1024
#define HID   512
#define LTILE 128
#define NQ    128

// ------------ device scratch ------------
__device__ __align__(16) __half g_ench[(size_t)BATCH * SEQ * HID];
__device__ __align__(16) __half g_wsh[HID * HID];
__device__ float g_projh[BATCH * HID];
__device__ float g_scores4[4][BATCH * SEQ];
__device__ float g_ctxpart[4][BATCH * HID];

// ------------ helpers ------------
__device__ __forceinline__ uint32_t smem_u32(const void* p) {
    uint32_t a;
    asm("{ .reg .u64 t; cvta.to.shared.u64 t, %1; cvt.u32.u64 %0, t; }" : "=r"(a) : "l"(p));
    return a;
}
__device__ __forceinline__ float fast_tanh(float x) {
    float y; asm("tanh.approx.f32 %0, %1;" : "=f"(y) : "f"(x)); return y;
}
__device__ __forceinline__ void ldsm4(uint32_t* r, uint32_t addr) {
    asm volatile("ldmatrix.sync.aligned.m8n8.x4.shared.b16 {%0,%1,%2,%3}, [%4];"
        : "=r"(r[0]), "=r"(r[1]), "=r"(r[2]), "=r"(r[3]) : "r"(addr));
}
// fp16-accumulator MMA (test: is fp32-accum HMMA half-rate on sm_103?)
__device__ __forceinline__ void mma16816h(uint32_t* c, const uint32_t* a, const uint32_t* b) {
    asm volatile("mma.sync.aligned.m16n8k16.row.col.f16.f16.f16.f16 "
        "{%0,%1}, {%2,%3,%4,%5}, {%6,%7}, {%0,%1};"
        : "+r"(c[0]), "+r"(c[1])
        : "r"(a[0]), "r"(a[1]), "r"(a[2]), "r"(a[3]), "r"(b[0]), "r"(b[1]));
}
__device__ __forceinline__ void cp16(uint32_t dst, const void* src) {
    asm volatile("cp.async.cg.shared.global [%0], [%1], 16;" :: "r"(dst), "l"(src) : "memory");
}
#define CP_COMMIT() asm volatile("cp.async.commit_group;" ::: "memory")

__device__ __forceinline__ void cvt8(const float* src, __half* dst, size_t i) {
    float4 x0 = *reinterpret_cast<const float4*>(src + i);
    float4 x1 = *reinterpret_cast<const float4*>(src + i + 4);
    __half2 h0 = __floats2half2_rn(x0.x, x0.y);
    __half2 h1 = __floats2half2_rn(x0.z, x0.w);
    __half2 h2 = __floats2half2_rn(x1.x, x1.y);
    __half2 h3 = __floats2half2_rn(x1.z, x1.w);
    uint4 o;
    o.x = *reinterpret_cast<uint32_t*>(&h0);
    o.y = *reinterpret_cast<uint32_t*>(&h1);
    o.z = *reinterpret_cast<uint32_t*>(&h2);
    o.w = *reinterpret_cast<uint32_t*>(&h3);
    *reinterpret_cast<uint4*>(dst + i) = o;
}

// ------------ K0a/K0b: conversions (separate so scores lands at launch idx 3) ------------
__global__ void __launch_bounds__(256) cvt_enc_kernel(const float* __restrict__ enc) {
    cvt8(enc, g_ench, ((size_t)blockIdx.x * 256 + threadIdx.x) * 8);
}
__global__ void __launch_bounds__(256) cvt_ws_kernel(const float* __restrict__ Ws) {
    cvt8(Ws, g_wsh, ((size_t)blockIdx.x * 256 + threadIdx.x) * 8);
}

// ------------ K1: proj_h ------------
__global__ void __launch_bounds__(256)
projh_kernel(const float* __restrict__ dec, const float* __restrict__ Wh) {
    __shared__ float4 dsm[8][HID / 4];
    const int half = blockIdx.x, bg = blockIdx.y, tid = threadIdx.x;
    for (int i = tid; i < 8 * (HID / 4); i += 256) {
        int bb = i >> 7, k4 = i & 127;
        dsm[bb][k4] = reinterpret_cast<const float4*>(dec + (size_t)(bg * 8 + bb) * HID)[k4];
    }
    __syncthreads();
    const int h = half * 256 + tid;
    const float4* wr = reinterpret_cast<const float4*>(Wh + (size_t)h * HID);
    float acc[8];
#pragma unroll
    for (int bb = 0; bb < 8; ++bb) acc[bb] = 0.f;
    for (int k4 = 0; k4 < HID / 4; ++k4) {
        float4 w = wr[k4];
#pragma unroll
        for (int bb = 0; bb < 8; ++bb) {
            float4 d = dsm[bb][k4];
            acc[bb] += w.x * d.x + w.y * d.y + w.z * d.z + w.w * d.w;
        }
    }
#pragma unroll
    for (int bb = 0; bb < 8; ++bb)
        g_projh[(size_t)(bg * 8 + bb) * HID + h] = acc[bb];
}

// ------------ K2: fused scores GEMM ------------
// 256 threads, M=128 x N=128, KTILE=64, 3-stage ring, prefetch-1,
// ONE barrier per iteration, fp16 accum per chunk promoted to fp32.
#define PAD_B   144
#define A_BYTES (128 * PAD_B)           // 18432
#define STAGE   (2 * A_BYTES)           // 36864
#define NSTAGE  3
#define OFF_PROJH 0
#define OFF_V     512
#define OFF_SC    1024
#define OFF_TILES 2048
#define K2_SMEM   (OFF_TILES + NSTAGE * STAGE)   // 112640

__global__ void __launch_bounds__(256, 2)
scores_kernel(const float* __restrict__ v) {
    extern __shared__ char smem[];
    const uint32_t sb = smem_u32(smem);
    const int tid = threadIdx.x, lane = tid & 31, w = tid >> 5;
    const int wm = w & 3, wn = w >> 2;            // 4 M-warps x 2 N-warps
    const int hq = blockIdx.x & 3, ltile = blockIdx.x >> 2, b = blockIdx.y;

    float* projh_sm = reinterpret_cast<float*>(smem + OFF_PROJH);
    float* v_sm     = reinterpret_cast<float*>(smem + OFF_V);
    if (tid < NQ) {
        projh_sm[tid] = g_projh[(size_t)b * HID + hq * NQ + tid];
        v_sm[tid]     = v[hq * NQ + tid];
    }

    const __half* Asrc = g_ench + ((size_t)b * SEQ + (size_t)ltile * LTILE) * HID;
    const __half* Bsrc = g_wsh + (size_t)hq * NQ * HID;

    const int rowA  = wm * 32 + (lane & 7) + ((lane >> 3) & 1) * 8;
    const int koffA = (lane >> 4) * 16;
    const uint32_t aoff0 = (uint32_t)(rowA * PAD_B + koffA);
    const uint32_t aoff1 = (uint32_t)((rowA + 16) * PAD_B + koffA);
    const int rowB  = wn * 64 + (lane & 7) + (lane >> 4) * 8;
    const int koffB = ((lane >> 3) & 1) * 16;
    const uint32_t boff = (uint32_t)(A_BYTES + rowB * PAD_B + koffB);

    float c32[2][8][4];
#pragma unroll
    for (int mt = 0; mt < 2; ++mt)
#pragma unroll
        for (int nf = 0; nf < 8; ++nf)
#pragma unroll
            for (int j = 0; j < 4; ++j) c32[mt][nf][j] = 0.f;

    auto load_chunk = [&](int kc, int buf) {
        uint32_t tb = sb + OFF_TILES + (uint32_t)buf * STAGE;
#pragma unroll
        for (int j = 0; j < 4; ++j) {     // A: 128 rows x 8 granules
            int idx = tid + j * 256;
            int r = idx >> 3, seg = idx & 7;
            cp16(tb + (uint32_t)(r * PAD_B + seg * 16),
                 Asrc + (size_t)r * HID + kc * 64 + seg * 8);
        }
#pragma unroll
        for (int j = 0; j < 4; ++j) {     // B: 128 rows x 8 granules
            int idx = tid + j * 256;
            int r = idx >> 3, seg = idx & 7;
            cp16(tb + A_BYTES + (uint32_t)(r * PAD_B + seg * 16),
                 Bsrc + (size_t)r * HID + kc * 64 + seg * 8);
        }
        CP_COMMIT();
    };

    load_chunk(0, 0);
#pragma unroll 1
    for (int kc = 0; kc < 8; ++kc) {
        if (kc < 7) {
            load_chunk(kc + 1, (kc + 1) % NSTAGE);
            asm volatile("cp.async.wait_group 1;" ::: "memory");
        } else {
            asm volatile("cp.async.wait_group 0;" ::: "memory");
        }
        // Single barrier. Safety: loader at iter kc writes buf (kc+1)%3; any
        // warp still in MMA is at iter kc-1 using buf (kc-1)%3; previous
        // content of (kc+1)%3 (chunk kc-2) was consumed before barrier kc-1,
        // which all warps have passed.
        __syncthreads();
        uint32_t tb = sb + OFF_TILES + (uint32_t)(kc % NSTAGE) * STAGE;

        uint32_t hc[2][8][2];
#pragma unroll
        for (int mt = 0; mt < 2; ++mt)
#pragma unroll
            for (int nf = 0; nf < 8; ++nf)
                hc[mt][nf][0] = hc[mt][nf][1] = 0u;

#pragma unroll
        for (int kk = 0; kk < 4; ++kk) {
            uint32_t a0[4], a1[4];
            ldsm4(a0, tb + aoff0 + kk * 32);
            ldsm4(a1, tb + aoff1 + kk * 32);
#pragma unroll
            for (int gi = 0; gi < 4; ++gi) {
                uint32_t bf[4];
                ldsm4(bf, tb + boff + (uint32_t)gi * (16 * PAD_B) + kk * 32);
                mma16816h(hc[0][gi * 2 + 0], a0, bf);
                mma16816h(hc[0][gi * 2 + 1], a0, bf + 2);
                mma16816h(hc[1][gi * 2 + 0], a1, bf);
                mma16816h(hc[1][gi * 2 + 1], a1, bf + 2);
            }
        }
        // promote chunk partials to fp32 master
#pragma unroll
        for (int mt = 0; mt < 2; ++mt)
#pragma unroll
            for (int nf = 0; nf < 8; ++nf) {
                float2 f0 = __half22float2(*reinterpret_cast<__half2*>(&hc[mt][nf][0]));
                float2 f1 = __half22float2(*reinterpret_cast<__half2*>(&hc[mt][nf][1]));
                c32[mt][nf][0] += f0.x;
                c32[mt][nf][1] += f0.y;
                c32[mt][nf][2] += f1.x;
                c32[mt][nf][3] += f1.y;
            }
    }

    // epilogue: tanh + v-dot over this quarter's 128 h-cols
    float part[2][2] = {{0.f, 0.f}, {0.f, 0.f}};
#pragma unroll
    for (int mt = 0; mt < 2; ++mt)
#pragma unroll
        for (int nf = 0; nf < 8; ++nf)
#pragma unroll
            for (int j = 0; j < 4; ++j) {
                int h = wn * 64 + (nf >> 1) * 16 + (nf & 1) * 8 + (lane & 3) * 2 + (j & 1);
                float p = c32[mt][nf][j] + projh_sm[h];
                part[mt][j >> 1] += v_sm[h] * fast_tanh(p);
            }
    float* sc = reinterpret_cast<float*>(smem + OFF_SC);
#pragma unroll
    for (int mt = 0; mt < 2; ++mt)
#pragma unroll
        for (int rp = 0; rp < 2; ++rp) {
            float val = part[mt][rp];
            val += __shfl_xor_sync(0xffffffffu, val, 1);
            val += __shfl_xor_sync(0xffffffffu, val, 2);
            if ((lane & 3) == 0)
                sc[wn * 128 + wm * 32 + mt * 16 + rp * 8 + (lane >> 2)] = val;
        }
    __syncthreads();
    if (tid < 128)
        g_scores4[hq][(size_t)b * SEQ + ltile * LTILE + tid] = sc[tid] + sc[128 + tid];
}

// ------------ K3: softmax -> alpha ------------
__global__ void __launch_bounds__(256)
softmax_kernel(float* __restrict__ alpha) {
    __shared__ float red[8];
    const int b = blockIdx.x, tid = threadIdx.x, wid = tid >> 5, lid = tid & 31;
    float s[4];
#pragma unroll
    for (int i = 0; i < 4; ++i) {
        size_t l = (size_t)b * SEQ + tid + i * 256;
        s[i] = (g_scores4[0][l] + g_scores4[1][l]) + (g_scores4[2][l] + g_scores4[3][l]);
    }
    float m = fmaxf(fmaxf(s[0], s[1]), fmaxf(s[2], s[3]));
#pragma unroll
    for (int o = 16; o; o >>= 1) m = fmaxf(m, __shfl_xor_sync(0xffffffffu, m, o));
    if (lid == 0) red[wid] = m;
    __syncthreads();
    m = red[0];
#pragma unroll
    for (int i = 1; i < 8; ++i) m = fmaxf(m, red[i]);
    __syncthreads();
    float e[4], sum = 0.f;
#pragma unroll
    for (int i = 0; i < 4; ++i) { e[i] = __expf(s[i] - m); sum += e[i]; }
#pragma unroll
    for (int o = 16; o; o >>= 1) sum += __shfl_xor_sync(0xffffffffu, sum, o);
    if (lid == 0) red[wid] = sum;
    __syncthreads();
    sum = 0.f;
#pragma unroll
    for (int i = 0; i < 8; ++i) sum += red[i];
    float inv = 1.0f / sum;
#pragma unroll
    for (int i = 0; i < 4; ++i)
        alpha[(size_t)b * SEQ + tid + i * 256] = e[i] * inv;
}

// ------------ K4: context partials, 4-way l-split ------------
__global__ void __launch_bounds__(256)
context_part_kernel(const float* __restrict__ alpha) {
    __shared__ float al[256];
    __shared__ float red[4][HID];
    const int lc = blockIdx.x, b = blockIdx.y, tid = threadIdx.x;
    al[tid] = alpha[(size_t)b * SEQ + lc * 256 + tid];
    __syncthreads();
    const int cg = tid & 63;
    const int ph = tid >> 6;
    const __half* ep = g_ench + ((size_t)b * SEQ + lc * 256) * HID + cg * 8;
    float acc[8];
#pragma unroll
    for (int j = 0; j < 8; ++j) acc[j] = 0.f;
#pragma unroll 4
    for (int l = ph; l < 256; l += 4) {
        uint4 u = *reinterpret_cast<const uint4*>(ep + (size_t)l * HID);
        float a = al[l];
        float2 f0 = __half22float2(*reinterpret_cast<__half2*>(&u.x));
        float2 f1 = __half22float2(*reinterpret_cast<__half2*>(&u.y));
        float2 f2 = __half22float2(*reinterpret_cast<__half2*>(&u.z));
        float2 f3 = __half22float2(*reinterpret_cast<__half2*>(&u.w));
        acc[0] += a * f0.x; acc[1] += a * f0.y;
        acc[2] += a * f1.x; acc[3] += a * f1.y;
        acc[4] += a * f2.x; acc[5] += a * f2.y;
        acc[6] += a * f3.x; acc[7] += a * f3.y;
    }
#pragma unroll
    for (int j = 0; j < 8; ++j) red[ph][cg * 8 + j] = acc[j];
    __syncthreads();
    for (int e = tid; e < HID; e += 256)
        g_ctxpart[lc][(size_t)b * HID + e] =
            (red[0][e] + red[1][e]) + (red[2][e] + red[3][e]);
}

// ------------ K5: reduce context partials ------------
__global__ void __launch_bounds__(512)
context_reduce_kernel(float* __restrict__ ctx) {
    const size_t i = (size_t)blockIdx.x * HID + threadIdx.x;
    ctx[i] = (g_ctxpart[0][i] + g_ctxpart[1][i]) + (g_ctxpart[2][i] + g_ctxpart[3][i]);
}

// ------------ launch ------------
extern "C" void kernel_launch(void* const* d_in, const int* in_sizes, int n_in,
                              void* d_out, int out_size) {
    const float* dec = (const float*)d_in[0];
    const float* enc = (const float*)d_in[1];
    const float* Wh  = (const float*)d_in[2];
    const float* Ws  = (const float*)d_in[3];
    const float* v   = (const float*)d_in[4];
    float* out   = (float*)d_out;
    float* ctx   = out;
    float* alpha = out + BATCH * HID;

    cudaFuncSetAttribute(scores_kernel, cudaFuncAttributeMaxDynamicSharedMemorySize, K2_SMEM);

    cvt_enc_kernel<<<(int)(((size_t)BATCH * SEQ * HID) / 2048), 256>>>(enc);   // idx 0
    cvt_ws_kernel<<<(HID * HID) / 2048, 256>>>(Ws);                            // idx 1
    projh_kernel<<<dim3(2, 32), 256>>>(dec, Wh);                               // idx 2
    scores_kernel<<<dim3(32, BATCH), 256, K2_SMEM>>>(v);                       // idx 3 (profiled)
    softmax_kernel<<<BATCH, 256>>>(alpha);
    context_part_kernel<<<dim3(4, BATCH), 256>>>(alpha);
    context_reduce_kernel<<<BATCH, 512>>>(ctx);
}

// round 11
// speedup vs baseline: 1.1073x; 1.1073x over previous
#include <cuda_runtime.h>
#include <cuda_fp16.h>
#include <cstdint>

#define BATCH 256
#define SEQ   1024
#define HID   512
#define LTILE 128
#define NQ    128

// ------------ device scratch ------------
__device__ __align__(16) __half g_ench[(size_t)BATCH * SEQ * HID];
__device__ __align__(16) __half g_wsh[HID * HID];
__device__ float g_projh[BATCH * HID];
__device__ float g_scores4[4][BATCH * SEQ];
__device__ float g_ctxpart[4][BATCH * HID];

// ------------ helpers ------------
__device__ __forceinline__ uint32_t smem_u32(const void* p) {
    uint32_t a;
    asm("{ .reg .u64 t; cvta.to.shared.u64 t, %1; cvt.u32.u64 %0, t; }" : "=r"(a) : "l"(p));
    return a;
}
__device__ __forceinline__ float fast_tanh(float x) {
    float y; asm("tanh.approx.f32 %0, %1;" : "=f"(y) : "f"(x)); return y;
}
__device__ __forceinline__ void ldsm4(uint32_t* r, uint32_t addr) {
    asm volatile("ldmatrix.sync.aligned.m8n8.x4.shared.b16 {%0,%1,%2,%3}, [%4];"
        : "=r"(r[0]), "=r"(r[1]), "=r"(r[2]), "=r"(r[3]) : "r"(addr));
}
__device__ __forceinline__ void mma16816(float* c, const uint32_t* a, const uint32_t* b) {
    asm volatile("mma.sync.aligned.m16n8k16.row.col.f32.f16.f16.f32 "
        "{%0,%1,%2,%3}, {%4,%5,%6,%7}, {%8,%9}, {%0,%1,%2,%3};"
        : "+f"(c[0]), "+f"(c[1]), "+f"(c[2]), "+f"(c[3])
        : "r"(a[0]), "r"(a[1]), "r"(a[2]), "r"(a[3]), "r"(b[0]), "r"(b[1]));
}
__device__ __forceinline__ void cp16(uint32_t dst, const void* src) {
    asm volatile("cp.async.cg.shared.global [%0], [%1], 16;" :: "r"(dst), "l"(src) : "memory");
}
#define CP_COMMIT() asm volatile("cp.async.commit_group;" ::: "memory")

__device__ __forceinline__ void cvt8(const float* src, __half* dst, size_t i) {
    float4 x0 = *reinterpret_cast<const float4*>(src + i);
    float4 x1 = *reinterpret_cast<const float4*>(src + i + 4);
    __half2 h0 = __floats2half2_rn(x0.x, x0.y);
    __half2 h1 = __floats2half2_rn(x0.z, x0.w);
    __half2 h2 = __floats2half2_rn(x1.x, x1.y);
    __half2 h3 = __floats2half2_rn(x1.z, x1.w);
    uint4 o;
    o.x = *reinterpret_cast<uint32_t*>(&h0);
    o.y = *reinterpret_cast<uint32_t*>(&h1);
    o.z = *reinterpret_cast<uint32_t*>(&h2);
    o.w = *reinterpret_cast<uint32_t*>(&h3);
    *reinterpret_cast<uint4*>(dst + i) = o;
}

// ------------ K0a/K0b: conversions (kept separate: scores stays at launch idx 3) ------------
__global__ void __launch_bounds__(256) cvt_enc_kernel(const float* __restrict__ enc) {
    cvt8(enc, g_ench, ((size_t)blockIdx.x * 256 + threadIdx.x) * 8);
}
__global__ void __launch_bounds__(256) cvt_ws_kernel(const float* __restrict__ Ws) {
    cvt8(Ws, g_wsh, ((size_t)blockIdx.x * 256 + threadIdx.x) * 8);
}

// ------------ K1: proj_h ------------
__global__ void __launch_bounds__(256)
projh_kernel(const float* __restrict__ dec, const float* __restrict__ Wh) {
    __shared__ float4 dsm[8][HID / 4];
    const int half = blockIdx.x, bg = blockIdx.y, tid = threadIdx.x;
    for (int i = tid; i < 8 * (HID / 4); i += 256) {
        int bb = i >> 7, k4 = i & 127;
        dsm[bb][k4] = reinterpret_cast<const float4*>(dec + (size_t)(bg * 8 + bb) * HID)[k4];
    }
    __syncthreads();
    const int h = half * 256 + tid;
    const float4* wr = reinterpret_cast<const float4*>(Wh + (size_t)h * HID);
    float acc[8];
#pragma unroll
    for (int bb = 0; bb < 8; ++bb) acc[bb] = 0.f;
    for (int k4 = 0; k4 < HID / 4; ++k4) {
        float4 w = wr[k4];
#pragma unroll
        for (int bb = 0; bb < 8; ++bb) {
            float4 d = dsm[bb][k4];
            acc[bb] += w.x * d.x + w.y * d.y + w.z * d.z + w.w * d.w;
        }
    }
#pragma unroll
    for (int bb = 0; bb < 8; ++bb)
        g_projh[(size_t)(bg * 8 + bb) * HID + h] = acc[bb];
}

// ------------ K2: fused scores GEMM ------------
// 512 threads (16 warps, 4M x 4N), M=128 x N=128, KTILE=64, 3-stage ring,
// prefetch-1, ONE barrier per iter, fp32 accum, 2 CTAs/SM -> 32 warps/SM.
#define PAD_B   144
#define A_BYTES (128 * PAD_B)           // 18432
#define STAGE   (2 * A_BYTES)           // 36864
#define NSTAGE  3
#define OFF_PROJH 0
#define OFF_V     512
#define OFF_SC    1024
#define OFF_TILES 4096
#define K2_SMEM   (OFF_TILES + NSTAGE * STAGE)   // 114688

__global__ void __launch_bounds__(512, 2)
scores_kernel(const float* __restrict__ v) {
    extern __shared__ char smem[];
    const uint32_t sb = smem_u32(smem);
    const int tid = threadIdx.x, lane = tid & 31, w = tid >> 5;
    const int wm = w & 3, wn = w >> 2;            // 4 M-warps x 4 N-warps
    const int hq = blockIdx.x & 3, ltile = blockIdx.x >> 2, b = blockIdx.y;

    float* projh_sm = reinterpret_cast<float*>(smem + OFF_PROJH);
    float* v_sm     = reinterpret_cast<float*>(smem + OFF_V);
    if (tid < NQ) {
        projh_sm[tid] = g_projh[(size_t)b * HID + hq * NQ + tid];
        v_sm[tid]     = v[hq * NQ + tid];
    }

    const __half* Asrc = g_ench + ((size_t)b * SEQ + (size_t)ltile * LTILE) * HID;
    const __half* Bsrc = g_wsh + (size_t)hq * NQ * HID;

    // warp tile: rows [wm*32, wm*32+32), cols [wn*32, wn*32+32)
    const int rowA  = wm * 32 + (lane & 7) + ((lane >> 3) & 1) * 8;
    const int koffA = (lane >> 4) * 16;
    const uint32_t aoff0 = (uint32_t)(rowA * PAD_B + koffA);
    const uint32_t aoff1 = (uint32_t)((rowA + 16) * PAD_B + koffA);
    const int rowB  = wn * 32 + (lane & 7) + (lane >> 4) * 8;
    const int koffB = ((lane >> 3) & 1) * 16;
    const uint32_t boff = (uint32_t)(A_BYTES + rowB * PAD_B + koffB);

    float c32[2][4][4];   // [mt][nf][j] -> 32 regs
#pragma unroll
    for (int mt = 0; mt < 2; ++mt)
#pragma unroll
        for (int nf = 0; nf < 4; ++nf)
#pragma unroll
            for (int j = 0; j < 4; ++j) c32[mt][nf][j] = 0.f;

    // A: 128 rows x 8 granules = 1024; B same; 2+2 granules per thread
    auto load_chunk = [&](int kc, int buf) {
        uint32_t tb = sb + OFF_TILES + (uint32_t)buf * STAGE;
#pragma unroll
        for (int j = 0; j < 2; ++j) {
            int idx = tid + j * 512;
            int r = idx >> 3, seg = idx & 7;
            cp16(tb + (uint32_t)(r * PAD_B + seg * 16),
                 Asrc + (size_t)r * HID + kc * 64 + seg * 8);
        }
#pragma unroll
        for (int j = 0; j < 2; ++j) {
            int idx = tid + j * 512;
            int r = idx >> 3, seg = idx & 7;
            cp16(tb + A_BYTES + (uint32_t)(r * PAD_B + seg * 16),
                 Bsrc + (size_t)r * HID + kc * 64 + seg * 8);
        }
        CP_COMMIT();
    };

    load_chunk(0, 0);
#pragma unroll 1
    for (int kc = 0; kc < 8; ++kc) {
        if (kc < 7) {
            load_chunk(kc + 1, (kc + 1) % NSTAGE);
            asm volatile("cp.async.wait_group 1;" ::: "memory");
        } else {
            asm volatile("cp.async.wait_group 0;" ::: "memory");
        }
        // Single barrier per iter. Loader at iter kc writes buf (kc+1)%3; any
        // lagging warp is in iter kc-1's MMAs on buf (kc-1)%3; buf (kc+1)%3's
        // old chunk (kc-2) was consumed before barrier kc-1 which all passed.
        __syncthreads();
        uint32_t tb = sb + OFF_TILES + (uint32_t)(kc % NSTAGE) * STAGE;
#pragma unroll
        for (int kk = 0; kk < 4; ++kk) {
            uint32_t a0[4], a1[4];
            ldsm4(a0, tb + aoff0 + kk * 32);
            ldsm4(a1, tb + aoff1 + kk * 32);
#pragma unroll
            for (int gi = 0; gi < 2; ++gi) {
                uint32_t bf[4];
                ldsm4(bf, tb + boff + (uint32_t)gi * (16 * PAD_B) + kk * 32);
                mma16816(c32[0][gi * 2 + 0], a0, bf);
                mma16816(c32[0][gi * 2 + 1], a0, bf + 2);
                mma16816(c32[1][gi * 2 + 0], a1, bf);
                mma16816(c32[1][gi * 2 + 1], a1, bf + 2);
            }
        }
    }

    // epilogue: tanh + v-dot over this warp's 32 h-cols
    float part[2][2] = {{0.f, 0.f}, {0.f, 0.f}};
#pragma unroll
    for (int mt = 0; mt < 2; ++mt)
#pragma unroll
        for (int nf = 0; nf < 4; ++nf)
#pragma unroll
            for (int j = 0; j < 4; ++j) {
                int h = wn * 32 + (nf >> 1) * 16 + (nf & 1) * 8 + (lane & 3) * 2 + (j & 1);
                float p = c32[mt][nf][j] + projh_sm[h];
                part[mt][j >> 1] += v_sm[h] * fast_tanh(p);
            }
    float* sc = reinterpret_cast<float*>(smem + OFF_SC);  // [wn][row] 4x128
#pragma unroll
    for (int mt = 0; mt < 2; ++mt)
#pragma unroll
        for (int rp = 0; rp < 2; ++rp) {
            float val = part[mt][rp];
            val += __shfl_xor_sync(0xffffffffu, val, 1);
            val += __shfl_xor_sync(0xffffffffu, val, 2);
            if ((lane & 3) == 0)
                sc[wn * 128 + wm * 32 + mt * 16 + rp * 8 + (lane >> 2)] = val;
        }
    __syncthreads();
    if (tid < 128)
        g_scores4[hq][(size_t)b * SEQ + ltile * LTILE + tid] =
            (sc[tid] + sc[128 + tid]) + (sc[256 + tid] + sc[384 + tid]);
}

// ------------ K3: softmax -> alpha ------------
__global__ void __launch_bounds__(256)
softmax_kernel(float* __restrict__ alpha) {
    __shared__ float red[8];
    const int b = blockIdx.x, tid = threadIdx.x, wid = tid >> 5, lid = tid & 31;
    float s[4];
#pragma unroll
    for (int i = 0; i < 4; ++i) {
        size_t l = (size_t)b * SEQ + tid + i * 256;
        s[i] = (g_scores4[0][l] + g_scores4[1][l]) + (g_scores4[2][l] + g_scores4[3][l]);
    }
    float m = fmaxf(fmaxf(s[0], s[1]), fmaxf(s[2], s[3]));
#pragma unroll
    for (int o = 16; o; o >>= 1) m = fmaxf(m, __shfl_xor_sync(0xffffffffu, m, o));
    if (lid == 0) red[wid] = m;
    __syncthreads();
    m = red[0];
#pragma unroll
    for (int i = 1; i < 8; ++i) m = fmaxf(m, red[i]);
    __syncthreads();
    float e[4], sum = 0.f;
#pragma unroll
    for (int i = 0; i < 4; ++i) { e[i] = __expf(s[i] - m); sum += e[i]; }
#pragma unroll
    for (int o = 16; o; o >>= 1) sum += __shfl_xor_sync(0xffffffffu, sum, o);
    if (lid == 0) red[wid] = sum;
    __syncthreads();
    sum = 0.f;
#pragma unroll
    for (int i = 0; i < 8; ++i) sum += red[i];
    float inv = 1.0f / sum;
#pragma unroll
    for (int i = 0; i < 4; ++i)
        alpha[(size_t)b * SEQ + tid + i * 256] = e[i] * inv;
}

// ------------ K4: context partials, 4-way l-split ------------
__global__ void __launch_bounds__(256)
context_part_kernel(const float* __restrict__ alpha) {
    __shared__ float al[256];
    __shared__ float red[4][HID];
    const int lc = blockIdx.x, b = blockIdx.y, tid = threadIdx.x;
    al[tid] = alpha[(size_t)b * SEQ + lc * 256 + tid];
    __syncthreads();
    const int cg = tid & 63;
    const int ph = tid >> 6;
    const __half* ep = g_ench + ((size_t)b * SEQ + lc * 256) * HID + cg * 8;
    float acc[8];
#pragma unroll
    for (int j = 0; j < 8; ++j) acc[j] = 0.f;
#pragma unroll 4
    for (int l = ph; l < 256; l += 4) {
        uint4 u = *reinterpret_cast<const uint4*>(ep + (size_t)l * HID);
        float a = al[l];
        float2 f0 = __half22float2(*reinterpret_cast<__half2*>(&u.x));
        float2 f1 = __half22float2(*reinterpret_cast<__half2*>(&u.y));
        float2 f2 = __half22float2(*reinterpret_cast<__half2*>(&u.z));
        float2 f3 = __half22float2(*reinterpret_cast<__half2*>(&u.w));
        acc[0] += a * f0.x; acc[1] += a * f0.y;
        acc[2] += a * f1.x; acc[3] += a * f1.y;
        acc[4] += a * f2.x; acc[5] += a * f2.y;
        acc[6] += a * f3.x; acc[7] += a * f3.y;
    }
#pragma unroll
    for (int j = 0; j < 8; ++j) red[ph][cg * 8 + j] = acc[j];
    __syncthreads();
    for (int e = tid; e < HID; e += 256)
        g_ctxpart[lc][(size_t)b * HID + e] =
            (red[0][e] + red[1][e]) + (red[2][e] + red[3][e]);
}

// ------------ K5: reduce context partials ------------
__global__ void __launch_bounds__(512)
context_reduce_kernel(float* __restrict__ ctx) {
    const size_t i = (size_t)blockIdx.x * HID + threadIdx.x;
    ctx[i] = (g_ctxpart[0][i] + g_ctxpart[1][i]) + (g_ctxpart[2][i] + g_ctxpart[3][i]);
}

// ------------ launch ------------
extern "C" void kernel_launch(void* const* d_in, const int* in_sizes, int n_in,
                              void* d_out, int out_size) {
    const float* dec = (const float*)d_in[0];
    const float* enc = (const float*)d_in[1];
    const float* Wh  = (const float*)d_in[2];
    const float* Ws  = (const float*)d_in[3];
    const float* v   = (const float*)d_in[4];
    float* out   = (float*)d_out;
    float* ctx   = out;
    float* alpha = out + BATCH * HID;

    cudaFuncSetAttribute(scores_kernel, cudaFuncAttributeMaxDynamicSharedMemorySize, K2_SMEM);

    cvt_enc_kernel<<<(int)(((size_t)BATCH * SEQ * HID) / 2048), 256>>>(enc);   // idx 0
    cvt_ws_kernel<<<(HID * HID) / 2048, 256>>>(Ws);                            // idx 1
    projh_kernel<<<dim3(2, 32), 256>>>(dec, Wh);                               // idx 2
    scores_kernel<<<dim3(32, BATCH), 512, K2_SMEM>>>(v);                       // idx 3 (profiled)
    softmax_kernel<<<BATCH, 256>>>(alpha);
    context_part_kernel<<<dim3(4, BATCH), 256>>>(alpha);
    context_reduce_kernel<<<BATCH, 512>>>(ctx);
}

// round 12
// speedup vs baseline: 1.1594x; 1.0471x over previous
#include <cuda_runtime.h>
#include <cuda_fp16.h>
#include <cstdint>

#define BATCH 256
#define SEQ   1024
#define HID   512
#define LTILE 128
#define NH    256

// ------------ device scratch ------------
__device__ __align__(16) __half g_ench[(size_t)BATCH * SEQ * HID];
__device__ __align__(16) __half g_wsh[HID * HID];
__device__ float g_projh[BATCH * HID];
__device__ float g_scores2[2][BATCH * SEQ];
__device__ float g_ctxpart[4][BATCH * HID];

// ------------ helpers ------------
__device__ __forceinline__ uint32_t smem_u32(const void* p) {
    uint32_t a;
    asm("{ .reg .u64 t; cvta.to.shared.u64 t, %1; cvt.u32.u64 %0, t; }" : "=r"(a) : "l"(p));
    return a;
}
__device__ __forceinline__ float fast_tanh(float x) {
    float y; asm("tanh.approx.f32 %0, %1;" : "=f"(y) : "f"(x)); return y;
}
__device__ __forceinline__ void ldsm4(uint32_t* r, uint32_t addr) {
    asm volatile("ldmatrix.sync.aligned.m8n8.x4.shared.b16 {%0,%1,%2,%3}, [%4];"
        : "=r"(r[0]), "=r"(r[1]), "=r"(r[2]), "=r"(r[3]) : "r"(addr));
}
// fp16-accumulator MMA: 2 c-regs per 16x8 tile -> 32x64 warp tile in 32 regs
__device__ __forceinline__ void mma16816h(uint32_t* c, const uint32_t* a, const uint32_t* b) {
    asm volatile("mma.sync.aligned.m16n8k16.row.col.f16.f16.f16.f16 "
        "{%0,%1}, {%2,%3,%4,%5}, {%6,%7}, {%0,%1};"
        : "+r"(c[0]), "+r"(c[1])
        : "r"(a[0]), "r"(a[1]), "r"(a[2]), "r"(a[3]), "r"(b[0]), "r"(b[1]));
}
__device__ __forceinline__ void cp16(uint32_t dst, const void* src) {
    asm volatile("cp.async.cg.shared.global [%0], [%1], 16;" :: "r"(dst), "l"(src) : "memory");
}
#define CP_COMMIT() asm volatile("cp.async.commit_group;" ::: "memory")

__device__ __forceinline__ void cvt8(const float* src, __half* dst, size_t i) {
    float4 x0 = *reinterpret_cast<const float4*>(src + i);
    float4 x1 = *reinterpret_cast<const float4*>(src + i + 4);
    __half2 h0 = __floats2half2_rn(x0.x, x0.y);
    __half2 h1 = __floats2half2_rn(x0.z, x0.w);
    __half2 h2 = __floats2half2_rn(x1.x, x1.y);
    __half2 h3 = __floats2half2_rn(x1.z, x1.w);
    uint4 o;
    o.x = *reinterpret_cast<uint32_t*>(&h0);
    o.y = *reinterpret_cast<uint32_t*>(&h1);
    o.z = *reinterpret_cast<uint32_t*>(&h2);
    o.w = *reinterpret_cast<uint32_t*>(&h3);
    *reinterpret_cast<uint4*>(dst + i) = o;
}

// ------------ K0a/K0b: conversions (separate: scores stays at launch idx 3) ------------
__global__ void __launch_bounds__(256) cvt_enc_kernel(const float* __restrict__ enc) {
    cvt8(enc, g_ench, ((size_t)blockIdx.x * 256 + threadIdx.x) * 8);
}
__global__ void __launch_bounds__(256) cvt_ws_kernel(const float* __restrict__ Ws) {
    cvt8(Ws, g_wsh, ((size_t)blockIdx.x * 256 + threadIdx.x) * 8);
}

// ------------ K1: proj_h ------------
__global__ void __launch_bounds__(256)
projh_kernel(const float* __restrict__ dec, const float* __restrict__ Wh) {
    __shared__ float4 dsm[8][HID / 4];
    const int half = blockIdx.x, bg = blockIdx.y, tid = threadIdx.x;
    for (int i = tid; i < 8 * (HID / 4); i += 256) {
        int bb = i >> 7, k4 = i & 127;
        dsm[bb][k4] = reinterpret_cast<const float4*>(dec + (size_t)(bg * 8 + bb) * HID)[k4];
    }
    __syncthreads();
    const int h = half * 256 + tid;
    const float4* wr = reinterpret_cast<const float4*>(Wh + (size_t)h * HID);
    float acc[8];
#pragma unroll
    for (int bb = 0; bb < 8; ++bb) acc[bb] = 0.f;
    for (int k4 = 0; k4 < HID / 4; ++k4) {
        float4 w = wr[k4];
#pragma unroll
        for (int bb = 0; bb < 8; ++bb) {
            float4 d = dsm[bb][k4];
            acc[bb] += w.x * d.x + w.y * d.y + w.z * d.z + w.w * d.w;
        }
    }
#pragma unroll
    for (int bb = 0; bb < 8; ++bb)
        g_projh[(size_t)(bg * 8 + bb) * HID + h] = acc[bb];
}

// ------------ K2: fused scores GEMM ------------
// 512 threads (16 warps, 4M x 4N, warp tile 32x64), CTA M=128 x N=256,
// KTILE=64, 2-stage ring with loads issued AFTER the barrier (single
// barrier/iter), fp16 accumulators across all K, 2 CTAs/SM -> 32 warps/SM.
#define PAD_B   144
#define A_BYTES (128 * PAD_B)           // 18432
#define B_BYTES (256 * PAD_B)           // 36864
#define STAGE   (A_BYTES + B_BYTES)     // 55296
#define NSTAGE  2
#define OFF_PROJH 0
#define OFF_V     1024
#define OFF_SC    2048
#define OFF_TILES 4096
#define K2_SMEM   (OFF_TILES + NSTAGE * STAGE)   // 114688

__global__ void __launch_bounds__(512, 2)
scores_kernel(const float* __restrict__ v) {
    extern __shared__ char smem[];
    const uint32_t sb = smem_u32(smem);
    const int tid = threadIdx.x, lane = tid & 31, w = tid >> 5;
    const int wm = w & 3, wn = w >> 2;            // 4 M-warps x 4 N-warps
    const int hhalf = blockIdx.x & 1, ltile = blockIdx.x >> 1, b = blockIdx.y;

    float* projh_sm = reinterpret_cast<float*>(smem + OFF_PROJH);
    float* v_sm     = reinterpret_cast<float*>(smem + OFF_V);
    if (tid < NH) {
        projh_sm[tid] = g_projh[(size_t)b * HID + hhalf * NH + tid];
        v_sm[tid]     = v[hhalf * NH + tid];
    }

    const __half* Asrc = g_ench + ((size_t)b * SEQ + (size_t)ltile * LTILE) * HID;
    const __half* Bsrc = g_wsh + (size_t)hhalf * NH * HID;

    const int rowA  = wm * 32 + (lane & 7) + ((lane >> 3) & 1) * 8;
    const int koffA = (lane >> 4) * 16;
    const uint32_t aoff0 = (uint32_t)(rowA * PAD_B + koffA);
    const uint32_t aoff1 = (uint32_t)((rowA + 16) * PAD_B + koffA);
    const int rowB  = wn * 64 + (lane & 7) + (lane >> 4) * 8;
    const int koffB = ((lane >> 3) & 1) * 16;
    const uint32_t boff = (uint32_t)(A_BYTES + rowB * PAD_B + koffB);

    uint32_t c16[2][8][2];   // [mt][nf][rp] packed fp16x2 -> 32 regs
#pragma unroll
    for (int mt = 0; mt < 2; ++mt)
#pragma unroll
        for (int nf = 0; nf < 8; ++nf)
            c16[mt][nf][0] = c16[mt][nf][1] = 0u;

    // A: 1024 granules (2/thread), B: 2048 granules (4/thread)
    auto load_chunk = [&](int kc, int buf) {
        uint32_t tb = sb + OFF_TILES + (uint32_t)buf * STAGE;
#pragma unroll
        for (int j = 0; j < 2; ++j) {
            int idx = tid + j * 512;
            int r = idx >> 3, seg = idx & 7;
            cp16(tb + (uint32_t)(r * PAD_B + seg * 16),
                 Asrc + (size_t)r * HID + kc * 64 + seg * 8);
        }
#pragma unroll
        for (int j = 0; j < 4; ++j) {
            int idx = tid + j * 512;
            int r = idx >> 3, seg = idx & 7;
            cp16(tb + A_BYTES + (uint32_t)(r * PAD_B + seg * 16),
                 Bsrc + (size_t)r * HID + kc * 64 + seg * 8);
        }
        CP_COMMIT();
    };

    load_chunk(0, 0);
#pragma unroll 1
    for (int kc = 0; kc < 8; ++kc) {
        asm volatile("cp.async.wait_group 0;" ::: "memory");
        __syncthreads();
        // Loads AFTER the barrier: every warp has finished iter kc-1's ldsm
        // reads of buf (kc+1)&1 before anyone overwrites it. Single barrier.
        if (kc < 7) load_chunk(kc + 1, (kc + 1) & 1);
        uint32_t tb = sb + OFF_TILES + (uint32_t)(kc & 1) * STAGE;
#pragma unroll
        for (int kk = 0; kk < 4; ++kk) {
            uint32_t a0[4], a1[4];
            ldsm4(a0, tb + aoff0 + kk * 32);
            ldsm4(a1, tb + aoff1 + kk * 32);
#pragma unroll
            for (int gi = 0; gi < 4; ++gi) {
                uint32_t bf[4];
                ldsm4(bf, tb + boff + (uint32_t)gi * (16 * PAD_B) + kk * 32);
                mma16816h(c16[0][gi * 2 + 0], a0, bf);
                mma16816h(c16[0][gi * 2 + 1], a0, bf + 2);
                mma16816h(c16[1][gi * 2 + 0], a1, bf);
                mma16816h(c16[1][gi * 2 + 1], a1, bf + 2);
            }
        }
    }

    // epilogue: unpack fp16 accums, tanh + v-dot over this warp's 64 h-cols
    float part[2][2] = {{0.f, 0.f}, {0.f, 0.f}};
#pragma unroll
    for (int mt = 0; mt < 2; ++mt)
#pragma unroll
        for (int nf = 0; nf < 8; ++nf)
#pragma unroll
            for (int rp = 0; rp < 2; ++rp) {
                float2 f = __half22float2(*reinterpret_cast<__half2*>(&c16[mt][nf][rp]));
                int h0 = wn * 64 + nf * 8 + (lane & 3) * 2;
                float p0 = f.x + projh_sm[h0];
                float p1 = f.y + projh_sm[h0 + 1];
                part[mt][rp] += v_sm[h0] * fast_tanh(p0) + v_sm[h0 + 1] * fast_tanh(p1);
            }
    float* sc = reinterpret_cast<float*>(smem + OFF_SC);  // [wn][row] 4x128
#pragma unroll
    for (int mt = 0; mt < 2; ++mt)
#pragma unroll
        for (int rp = 0; rp < 2; ++rp) {
            float val = part[mt][rp];
            val += __shfl_xor_sync(0xffffffffu, val, 1);
            val += __shfl_xor_sync(0xffffffffu, val, 2);
            if ((lane & 3) == 0)
                sc[wn * 128 + wm * 32 + mt * 16 + rp * 8 + (lane >> 2)] = val;
        }
    __syncthreads();
    if (tid < 128)
        g_scores2[hhalf][(size_t)b * SEQ + ltile * LTILE + tid] =
            (sc[tid] + sc[128 + tid]) + (sc[256 + tid] + sc[384 + tid]);
}

// ------------ K3: softmax -> alpha ------------
__global__ void __launch_bounds__(256)
softmax_kernel(float* __restrict__ alpha) {
    __shared__ float red[8];
    const int b = blockIdx.x, tid = threadIdx.x, wid = tid >> 5, lid = tid & 31;
    float s[4];
#pragma unroll
    for (int i = 0; i < 4; ++i) {
        size_t l = (size_t)b * SEQ + tid + i * 256;
        s[i] = g_scores2[0][l] + g_scores2[1][l];
    }
    float m = fmaxf(fmaxf(s[0], s[1]), fmaxf(s[2], s[3]));
#pragma unroll
    for (int o = 16; o; o >>= 1) m = fmaxf(m, __shfl_xor_sync(0xffffffffu, m, o));
    if (lid == 0) red[wid] = m;
    __syncthreads();
    m = red[0];
#pragma unroll
    for (int i = 1; i < 8; ++i) m = fmaxf(m, red[i]);
    __syncthreads();
    float e[4], sum = 0.f;
#pragma unroll
    for (int i = 0; i < 4; ++i) { e[i] = __expf(s[i] - m); sum += e[i]; }
#pragma unroll
    for (int o = 16; o; o >>= 1) sum += __shfl_xor_sync(0xffffffffu, sum, o);
    if (lid == 0) red[wid] = sum;
    __syncthreads();
    sum = 0.f;
#pragma unroll
    for (int i = 0; i < 8; ++i) sum += red[i];
    float inv = 1.0f / sum;
#pragma unroll
    for (int i = 0; i < 4; ++i)
        alpha[(size_t)b * SEQ + tid + i * 256] = e[i] * inv;
}

// ------------ K4: context partials, 4-way l-split ------------
__global__ void __launch_bounds__(256)
context_part_kernel(const float* __restrict__ alpha) {
    __shared__ float al[256];
    __shared__ float red[4][HID];
    const int lc = blockIdx.x, b = blockIdx.y, tid = threadIdx.x;
    al[tid] = alpha[(size_t)b * SEQ + lc * 256 + tid];
    __syncthreads();
    const int cg = tid & 63;
    const int ph = tid >> 6;
    const __half* ep = g_ench + ((size_t)b * SEQ + lc * 256) * HID + cg * 8;
    float acc[8];
#pragma unroll
    for (int j = 0; j < 8; ++j) acc[j] = 0.f;
#pragma unroll 4
    for (int l = ph; l < 256; l += 4) {
        uint4 u = *reinterpret_cast<const uint4*>(ep + (size_t)l * HID);
        float a = al[l];
        float2 f0 = __half22float2(*reinterpret_cast<__half2*>(&u.x));
        float2 f1 = __half22float2(*reinterpret_cast<__half2*>(&u.y));
        float2 f2 = __half22float2(*reinterpret_cast<__half2*>(&u.z));
        float2 f3 = __half22float2(*reinterpret_cast<__half2*>(&u.w));
        acc[0] += a * f0.x; acc[1] += a * f0.y;
        acc[2] += a * f1.x; acc[3] += a * f1.y;
        acc[4] += a * f2.x; acc[5] += a * f2.y;
        acc[6] += a * f3.x; acc[7] += a * f3.y;
    }
#pragma unroll
    for (int j = 0; j < 8; ++j) red[ph][cg * 8 + j] = acc[j];
    __syncthreads();
    for (int e = tid; e < HID; e += 256)
        g_ctxpart[lc][(size_t)b * HID + e] =
            (red[0][e] + red[1][e]) + (red[2][e] + red[3][e]);
}

// ------------ K5: reduce context partials ------------
__global__ void __launch_bounds__(512)
context_reduce_kernel(float* __restrict__ ctx) {
    const size_t i = (size_t)blockIdx.x * HID + threadIdx.x;
    ctx[i] = (g_ctxpart[0][i] + g_ctxpart[1][i]) + (g_ctxpart[2][i] + g_ctxpart[3][i]);
}

// ------------ launch ------------
extern "C" void kernel_launch(void* const* d_in, const int* in_sizes, int n_in,
                              void* d_out, int out_size) {
    const float* dec = (const float*)d_in[0];
    const float* enc = (const float*)d_in[1];
    const float* Wh  = (const float*)d_in[2];
    const float* Ws  = (const float*)d_in[3];
    const float* v   = (const float*)d_in[4];
    float* out   = (float*)d_out;
    float* ctx   = out;
    float* alpha = out + BATCH * HID;

    cudaFuncSetAttribute(scores_kernel, cudaFuncAttributeMaxDynamicSharedMemorySize, K2_SMEM);

    cvt_enc_kernel<<<(int)(((size_t)BATCH * SEQ * HID) / 2048), 256>>>(enc);   // idx 0
    cvt_ws_kernel<<<(HID * HID) / 2048, 256>>>(Ws);                            // idx 1
    projh_kernel<<<dim3(2, 32), 256>>>(dec, Wh);                               // idx 2
    scores_kernel<<<dim3(16, BATCH), 512, K2_SMEM>>>(v);                       // idx 3 (profiled)
    softmax_kernel<<<BATCH, 256>>>(alpha);
    context_part_kernel<<<dim3(4, BATCH), 256>>>(alpha);
    context_reduce_kernel<<<BATCH, 512>>>(ctx);
}